// round 4
// baseline (speedup 1.0000x reference)
#include <cuda_runtime.h>
#include <cuda_bf16.h>

// Involution: B=4, C=256, G=16, K=7, S=1, P=3, H=W=56
#define HW 3136

__device__ float g_h[4 * 64 * HW];   // h = reduce(x): (4,64,3136) fp32

// ---- f32x2 helpers ----
union F2 { float2 f; unsigned long long u; };
__device__ __forceinline__ unsigned long long pk2f(float lo, float hi) {
    unsigned long long d;
    asm("mov.b64 %0, {%1, %2};" : "=l"(d) : "f"(lo), "f"(hi));
    return d;
}
__device__ __forceinline__ void unpk2(unsigned long long v, float& lo, float& hi) {
    asm("mov.b64 {%0, %1}, %2;" : "=f"(lo), "=f"(hi) : "l"(v));
}
__device__ __forceinline__ unsigned long long ffma2(
    unsigned long long a, unsigned long long b, unsigned long long c) {
    unsigned long long d;
    asm("fma.rn.f32x2 %0, %1, %2, %3;" : "=l"(d) : "l"(a), "l"(b), "l"(c));
    return d;
}
__device__ __forceinline__ unsigned long long add2(
    unsigned long long a, unsigned long long b) {
    unsigned long long d;
    asm("add.rn.f32x2 %0, %1, %2;" : "=l"(d) : "l"(a), "l"(b));
    return d;
}

// ---------------------------------------------------------------------------
// Kernel 1: h[b,o,p] = sum_c x[b,c,p]*rw[o,c] + rb[o]
// grid (28,4), block 256 (224 active). Tile: 4 o x 8 px (4 stride-28 pairs),
// k-paired weight loads (LDS.64), FFMA2 throughout.
// ---------------------------------------------------------------------------
__global__ __launch_bounds__(256) void reduce_kernel(
    const float* __restrict__ x,
    const float* __restrict__ rw,
    const float* __restrict__ rb)
{
    const int b  = blockIdx.y;
    const int n0 = blockIdx.x * 112;
    __shared__ float ws[64 * 32];    // [o][k]
    __shared__ float xs[32 * 112];   // [k][p]

    const int tid = threadIdx.x;
    const int og = tid / 14;         // 0..18 (active <16)
    const int pg = tid % 14;
    const int o0 = og * 4;
    const bool act = (tid < 224);

    unsigned long long acc[4][4];
    #pragma unroll
    for (int i = 0; i < 4; i++)
        #pragma unroll
        for (int m = 0; m < 4; m++) acc[i][m] = 0ull;

    for (int kb = 0; kb < 256; kb += 32) {
        #pragma unroll
        for (int i = 0; i < 8; i++) {
            int e = tid + i * 256;
            ws[e] = rw[(e >> 5) * 256 + kb + (e & 31)];
        }
        #pragma unroll
        for (int i = 0; i < 14; i++) {
            int e = tid + i * 256;
            int k = e / 112, p = e - k * 112;
            xs[e] = x[(b * 256 + kb + k) * HW + n0 + p];
        }
        __syncthreads();

        if (act) {
            #pragma unroll 2
            for (int k2 = 0; k2 < 16; k2++) {
                unsigned long long w2[4], h0[4], h1[4];
                #pragma unroll
                for (int i = 0; i < 4; i++) {
                    F2 t; t.f = *(const float2*)&ws[(o0 + i) * 32 + 2 * k2];
                    w2[i] = t.u;
                }
                #pragma unroll
                for (int m = 0; m < 4; m++) {
                    F2 t; t.f = *(const float2*)&xs[(2 * k2) * 112 + 2 * pg + 28 * m];
                    h0[m] = t.u;
                }
                #pragma unroll
                for (int m = 0; m < 4; m++) {
                    F2 t; t.f = *(const float2*)&xs[(2 * k2 + 1) * 112 + 2 * pg + 28 * m];
                    h1[m] = t.u;
                }
                #pragma unroll
                for (int i = 0; i < 4; i++) {
                    float wl, wh;
                    unpk2(w2[i], wl, wh);
                    unsigned long long wll = pk2f(wl, wl);
                    unsigned long long whh = pk2f(wh, wh);
                    #pragma unroll
                    for (int m = 0; m < 4; m++) acc[i][m] = ffma2(wll, h0[m], acc[i][m]);
                    #pragma unroll
                    for (int m = 0; m < 4; m++) acc[i][m] = ffma2(whh, h1[m], acc[i][m]);
                }
            }
        }
        __syncthreads();
    }

    if (act) {
        #pragma unroll
        for (int i = 0; i < 4; i++) {
            float bias = rb[o0 + i];
            unsigned long long bd = pk2f(bias, bias);
            #pragma unroll
            for (int m = 0; m < 4; m++) {
                F2 r; r.u = add2(acc[i][m], bd);
                *(float2*)&g_h[(b * 64 + o0 + i) * HW + n0 + 2 * pg + 28 * m] = r.f;
            }
        }
    }
}

// ---------------------------------------------------------------------------
// Kernel 2 (fused span GEMM + apply). grid (14,16,4), block 256, 2 CTAs/SM.
// Phase 1: kern = ws @ hs. kkg = tid%7 (warp-balanced, h loads dedup to 1 wf),
//          c-paired w loads, FFMA2. kern overlays the hs buffer.
// Phase 2: thread tile = 4 channels x 4 pixels (2 FFMA2 pairs); x row window
//          of 5 aligned LDS.64 serves 7 taps; kern reads broadcast over the
//          4 channel-lanes. xt channel stride 622 (bank-uniform).
// ---------------------------------------------------------------------------
#define XCH 622   // xt per-channel stride in floats

__global__ __launch_bounds__(256, 2) void inv_kernel(
    const float* __restrict__ x,
    const float* __restrict__ sw,
    const float* __restrict__ sb,
    float* __restrict__ out)
{
    const int r0 = blockIdx.x * 4;
    const int g  = blockIdx.y;
    const int b  = blockIdx.z;

    extern __shared__ float smem[];
    float* ws    = smem;             // 3136 : span_w[g][49][64]
    float* sbias = ws + 3136;        // 64
    float* hsk   = sbias + 64;       // 14336 : h[c][224], later kern[49][224]
    float* xt    = hsk + 64 * 224;   // 16*622 : x halo 16ch x (10r x 62c)

    const int tid = threadIdx.x;

    // ---- stage loads ----
    {
        const float4* swv = (const float4*)(sw + g * 49 * 64);
        float4* wsv = (float4*)ws;
        #pragma unroll
        for (int i = 0; i < 4; i++) {
            int e = tid + i * 256;
            if (e < 784) wsv[e] = swv[e];
        }
    }
    if (tid < 49) sbias[tid] = sb[g * 49 + tid];

    {
        float4* hsv = (float4*)hsk;
        #pragma unroll
        for (int i = 0; i < 14; i++) {
            int e = tid + i * 256;
            int c = e / 56, p4 = e - c * 56;
            hsv[e] = *(const float4*)&g_h[(b * 64 + c) * HW + r0 * 56 + p4 * 4];
        }
    }

    {
        #pragma unroll
        for (int i = 0; i < 39; i++) {
            int e = tid + i * 256;
            if (e < 16 * 620) {
                int cg  = e / 620;
                int rem = e - cg * 620;
                int rr  = rem / 62, cc = rem - rr * 62;
                int gr = r0 + rr - 3;
                int gc = cc - 3;
                float v = 0.f;
                if (gr >= 0 && gr < 56 && gc >= 0 && gc < 56)
                    v = x[(b * 256 + g * 16 + cg) * HW + gr * 56 + gc];
                xt[cg * XCH + rem] = v;
            }
        }
    }
    __syncthreads();

    // ---- Phase 1: kern = ws @ hs ----
    const int kkg  = tid % 7;        // warp-balanced
    const int pixg = tid / 7;        // 0..27 active (tid<196)
    const bool p1act = (tid < 196);

    unsigned long long kacc[7][4];
    #pragma unroll
    for (int i = 0; i < 7; i++)
        #pragma unroll
        for (int j = 0; j < 4; j++) kacc[i][j] = 0ull;

    if (p1act) {
        const float* wrow = ws + kkg * 7 * 64;
        #pragma unroll 1
        for (int c2 = 0; c2 < 32; c2++) {
            unsigned long long w2[7], h0[4], h1[4];
            #pragma unroll
            for (int i = 0; i < 7; i++) {
                F2 t; t.f = *(const float2*)&wrow[i * 64 + 2 * c2];
                w2[i] = t.u;
            }
            #pragma unroll
            for (int j = 0; j < 4; j++) {
                F2 t; t.f = *(const float2*)&hsk[(2 * c2) * 224 + 2 * pixg + 56 * j];
                h0[j] = t.u;
            }
            #pragma unroll
            for (int j = 0; j < 4; j++) {
                F2 t; t.f = *(const float2*)&hsk[(2 * c2 + 1) * 224 + 2 * pixg + 56 * j];
                h1[j] = t.u;
            }
            #pragma unroll
            for (int i = 0; i < 7; i++) {
                float wl, wh;
                unpk2(w2[i], wl, wh);
                unsigned long long wll = pk2f(wl, wl);
                unsigned long long whh = pk2f(wh, wh);
                #pragma unroll
                for (int j = 0; j < 4; j++) kacc[i][j] = ffma2(wll, h0[j], kacc[i][j]);
                #pragma unroll
                for (int j = 0; j < 4; j++) kacc[i][j] = ffma2(whh, h1[j], kacc[i][j]);
            }
        }
    }
    __syncthreads();   // all hs reads complete before kern overwrite

    if (p1act) {
        #pragma unroll
        for (int i = 0; i < 7; i++) {
            float bias = sbias[kkg * 7 + i];
            unsigned long long bd = pk2f(bias, bias);
            #pragma unroll
            for (int j = 0; j < 4; j++) {
                F2 r; r.u = add2(kacc[i][j], bd);
                *(float2*)&hsk[(kkg * 7 + i) * 224 + 2 * pixg + 56 * j] = r.f;
            }
        }
    }
    __syncthreads();

    // ---- Phase 2: apply. thread = (quad q, channel-group cgrp) ----
    if (tid < 224) {
        const int q    = tid >> 2;      // 0..55
        const int cgrp = tid & 3;       // 0..3
        const int lr   = q / 14;        // 0..3
        const int qc   = q - lr * 14;   // 0..13
        const int c0   = qc * 4;        // first col of quad

        unsigned long long acc[4][2];
        #pragma unroll
        for (int i = 0; i < 4; i++)
            #pragma unroll
            for (int j = 0; j < 2; j++) acc[i][j] = 0ull;

        #pragma unroll 1
        for (int kh = 0; kh < 7; kh++) {
            unsigned long long kc2[7][2];
            #pragma unroll
            for (int kw = 0; kw < 7; kw++)
                #pragma unroll
                for (int j = 0; j < 2; j++) {
                    F2 t; t.f = *(const float2*)&hsk[(kh * 7 + kw) * 224 + lr * 56 + c0 + 2 * j];
                    kc2[kw][j] = t.u;
                }

            #pragma unroll
            for (int i = 0; i < 4; i++) {
                const int ch = cgrp * 4 + i;
                const float* xr = &xt[ch * XCH + (lr + kh) * 62 + c0];
                F2 P[5];
                #pragma unroll
                for (int s = 0; s < 5; s++) P[s].f = *(const float2*)&xr[2 * s];
                unsigned long long M[4];
                #pragma unroll
                for (int s = 0; s < 4; s++) M[s] = pk2f(P[s].f.y, P[s + 1].f.x);

                #pragma unroll
                for (int kw = 0; kw < 7; kw++) {
                    #pragma unroll
                    for (int j = 0; j < 2; j++) {
                        const int idx = 2 * j + kw;
                        unsigned long long xop = (idx & 1) ? M[idx >> 1] : P[idx >> 1].u;
                        acc[i][j] = ffma2(kc2[kw][j], xop, acc[i][j]);
                    }
                }
            }
        }

        const int row = r0 + lr;
        #pragma unroll
        for (int i = 0; i < 4; i++) {
            const int ch = cgrp * 4 + i;
            #pragma unroll
            for (int j = 0; j < 2; j++) {
                F2 r; r.u = acc[i][j];
                *(float2*)&out[(b * 256 + g * 16 + ch) * HW + row * 56 + c0 + 2 * j] = r.f;
            }
        }
    }
}

extern "C" void kernel_launch(void* const* d_in, const int* in_sizes, int n_in,
                              void* d_out, int out_size)
{
    const float* x  = (const float*)d_in[0];
    const float* rw = (const float*)d_in[1];
    const float* rb = (const float*)d_in[2];
    const float* sw = (const float*)d_in[3];
    const float* sb = (const float*)d_in[4];
    float* out = (float*)d_out;

    const int smem2 = (3136 + 64 + 64 * 224 + 16 * XCH) * sizeof(float); // ~110 KB
    cudaFuncSetAttribute(inv_kernel, cudaFuncAttributeMaxDynamicSharedMemorySize, smem2);

    reduce_kernel<<<dim3(28, 4), 256>>>(x, rw, rb);
    inv_kernel<<<dim3(14, 16, 4), 256, smem2>>>(x, sw, sb, out);
}

// round 5
// speedup vs baseline: 1.5709x; 1.5709x over previous
#include <cuda_runtime.h>
#include <cuda_bf16.h>

// Involution: B=4, C=256, G=16, K=7, S=1, P=3, H=W=56
#define HW 3136

__device__ float g_h[4 * 64 * HW];   // h = reduce(x): (4,64,3136) fp32

// ---- f32x2 helpers ----
union F2 { float2 f; unsigned long long u; };
__device__ __forceinline__ unsigned long long pk2f(float lo, float hi) {
    unsigned long long d;
    asm("mov.b64 %0, {%1, %2};" : "=l"(d) : "f"(lo), "f"(hi));
    return d;
}
__device__ __forceinline__ void unpk2(unsigned long long v, float& lo, float& hi) {
    asm("mov.b64 {%0, %1}, %2;" : "=f"(lo), "=f"(hi) : "l"(v));
}
__device__ __forceinline__ unsigned long long ffma2(
    unsigned long long a, unsigned long long b, unsigned long long c) {
    unsigned long long d;
    asm("fma.rn.f32x2 %0, %1, %2, %3;" : "=l"(d) : "l"(a), "l"(b), "l"(c));
    return d;
}
__device__ __forceinline__ unsigned long long add2(
    unsigned long long a, unsigned long long b) {
    unsigned long long d;
    asm("add.rn.f32x2 %0, %1, %2;" : "=l"(d) : "l"(a), "l"(b));
    return d;
}

// ---------------------------------------------------------------------------
// Kernel 1: h[b,o,p] = sum_c x[b,c,p]*rw[o,c] + rb[o]
// grid (28,4), block 256 (224 active). Tile: 4 o x 8 px, k-paired, FFMA2.
// ---------------------------------------------------------------------------
__global__ __launch_bounds__(256) void reduce_kernel(
    const float* __restrict__ x,
    const float* __restrict__ rw,
    const float* __restrict__ rb)
{
    const int b  = blockIdx.y;
    const int n0 = blockIdx.x * 112;
    __shared__ float ws[64 * 32];    // [o][k]
    __shared__ float xs[32 * 112];   // [k][p]

    const int tid = threadIdx.x;
    const int og = tid / 14;
    const int pg = tid % 14;
    const int o0 = og * 4;
    const bool act = (tid < 224);

    unsigned long long acc[4][4];
    #pragma unroll
    for (int i = 0; i < 4; i++)
        #pragma unroll
        for (int m = 0; m < 4; m++) acc[i][m] = 0ull;

    for (int kb = 0; kb < 256; kb += 32) {
        #pragma unroll
        for (int i = 0; i < 8; i++) {
            int e = tid + i * 256;
            ws[e] = rw[(e >> 5) * 256 + kb + (e & 31)];
        }
        #pragma unroll
        for (int i = 0; i < 14; i++) {
            int e = tid + i * 256;
            int k = e / 112, p = e - k * 112;
            xs[e] = x[(b * 256 + kb + k) * HW + n0 + p];
        }
        __syncthreads();

        if (act) {
            #pragma unroll 2
            for (int k2 = 0; k2 < 16; k2++) {
                unsigned long long w2[4], h0[4], h1[4];
                #pragma unroll
                for (int i = 0; i < 4; i++) {
                    F2 t; t.f = *(const float2*)&ws[(o0 + i) * 32 + 2 * k2];
                    w2[i] = t.u;
                }
                #pragma unroll
                for (int m = 0; m < 4; m++) {
                    F2 t; t.f = *(const float2*)&xs[(2 * k2) * 112 + 2 * pg + 28 * m];
                    h0[m] = t.u;
                }
                #pragma unroll
                for (int m = 0; m < 4; m++) {
                    F2 t; t.f = *(const float2*)&xs[(2 * k2 + 1) * 112 + 2 * pg + 28 * m];
                    h1[m] = t.u;
                }
                #pragma unroll
                for (int i = 0; i < 4; i++) {
                    float wl, wh;
                    unpk2(w2[i], wl, wh);
                    unsigned long long wll = pk2f(wl, wl);
                    unsigned long long whh = pk2f(wh, wh);
                    #pragma unroll
                    for (int m = 0; m < 4; m++) acc[i][m] = ffma2(wll, h0[m], acc[i][m]);
                    #pragma unroll
                    for (int m = 0; m < 4; m++) acc[i][m] = ffma2(whh, h1[m], acc[i][m]);
                }
            }
        }
        __syncthreads();
    }

    if (act) {
        #pragma unroll
        for (int i = 0; i < 4; i++) {
            float bias = rb[o0 + i];
            unsigned long long bd = pk2f(bias, bias);
            #pragma unroll
            for (int m = 0; m < 4; m++) {
                F2 r; r.u = add2(acc[i][m], bd);
                *(float2*)&g_h[(b * 64 + o0 + i) * HW + n0 + 2 * pg + 28 * m] = r.f;
            }
        }
    }
}

// ---------------------------------------------------------------------------
// Kernel 2 (fused span GEMM + apply). grid (14,16,4), block 256, 2 CTAs/SM.
// Phase 1: kern = ws @ hs. kkg=tid/28 (broadcast w, bank-safe), c-paired w
//          loads, FFMA2, 7kk x 8px per thread. kern overlays hs buffer.
// Phase 2: thread = pixel-pair (pp=tid>>1) x 8 channels (hh=tid&1).
//          kern loads: dense stride-2 float2 = 1 wf; x window: 4 aligned
//          LDS.64 + 3 packs serve 7 FFMA2/ch. XCH=642 (== 2 mod 32) keeps
//          every x load at the 2-wf dense minimum.
// ---------------------------------------------------------------------------
#define XCH 642   // xt per-channel stride in floats (== 2 mod 32, even)

__global__ __launch_bounds__(256, 2) void inv_kernel(
    const float* __restrict__ x,
    const float* __restrict__ sw,
    const float* __restrict__ sb,
    float* __restrict__ out)
{
    const int r0 = blockIdx.x * 4;
    const int g  = blockIdx.y;
    const int b  = blockIdx.z;

    extern __shared__ float smem[];
    float* ws    = smem;             // 3136 : span_w[g][49][64]
    float* sbias = ws + 3136;        // 64
    float* hsk   = sbias + 64;       // 14336 : h[c][224], later kern[49][224]
    float* xt    = hsk + 64 * 224;   // 16*642 : x halo 16ch x (10r x 62c)

    const int tid = threadIdx.x;

    // ---- stage loads ----
    {
        const float4* swv = (const float4*)(sw + g * 49 * 64);
        float4* wsv = (float4*)ws;
        #pragma unroll
        for (int i = 0; i < 4; i++) {
            int e = tid + i * 256;
            if (e < 784) wsv[e] = swv[e];
        }
    }
    if (tid < 49) sbias[tid] = sb[g * 49 + tid];

    {
        float4* hsv = (float4*)hsk;
        #pragma unroll
        for (int i = 0; i < 14; i++) {
            int e = tid + i * 256;
            int c = e / 56, p4 = e - c * 56;
            hsv[e] = *(const float4*)&g_h[(b * 64 + c) * HW + r0 * 56 + p4 * 4];
        }
    }

    {
        #pragma unroll
        for (int i = 0; i < 39; i++) {
            int e = tid + i * 256;
            if (e < 16 * 620) {
                int cg  = e / 620;
                int rem = e - cg * 620;
                int rr  = rem / 62, cc = rem - rr * 62;
                int gr = r0 + rr - 3;
                int gc = cc - 3;
                float v = 0.f;
                if (gr >= 0 && gr < 56 && gc >= 0 && gc < 56)
                    v = x[(b * 256 + g * 16 + cg) * HW + gr * 56 + gc];
                xt[cg * XCH + rem] = v;
            }
        }
    }
    __syncthreads();

    // ---- Phase 1: kern = ws @ hs (kkg=tid/28, c-paired w, FFMA2) ----
    const int kkg  = tid / 28;       // 0..6 active (7,8,9 idle)
    const int pixg = tid % 28;
    const bool p1act = (kkg < 7);

    unsigned long long kacc[7][4];
    #pragma unroll
    for (int i = 0; i < 7; i++)
        #pragma unroll
        for (int j = 0; j < 4; j++) kacc[i][j] = 0ull;

    if (p1act) {
        const float* wrow = ws + kkg * 7 * 64;
        #pragma unroll 1
        for (int c2 = 0; c2 < 32; c2++) {
            unsigned long long w2[7], h0[4], h1[4];
            #pragma unroll
            for (int i = 0; i < 7; i++) {
                F2 t; t.f = *(const float2*)&wrow[i * 64 + 2 * c2];
                w2[i] = t.u;
            }
            #pragma unroll
            for (int j = 0; j < 4; j++) {
                F2 t; t.f = *(const float2*)&hsk[(2 * c2) * 224 + 2 * pixg + 56 * j];
                h0[j] = t.u;
            }
            #pragma unroll
            for (int j = 0; j < 4; j++) {
                F2 t; t.f = *(const float2*)&hsk[(2 * c2 + 1) * 224 + 2 * pixg + 56 * j];
                h1[j] = t.u;
            }
            #pragma unroll
            for (int i = 0; i < 7; i++) {
                float wl, wh;
                unpk2(w2[i], wl, wh);
                unsigned long long wll = pk2f(wl, wl);
                unsigned long long whh = pk2f(wh, wh);
                #pragma unroll
                for (int j = 0; j < 4; j++) kacc[i][j] = ffma2(wll, h0[j], kacc[i][j]);
                #pragma unroll
                for (int j = 0; j < 4; j++) kacc[i][j] = ffma2(whh, h1[j], kacc[i][j]);
            }
        }
    }
    __syncthreads();   // all hs reads complete before kern overwrite

    if (p1act) {
        #pragma unroll
        for (int i = 0; i < 7; i++) {
            float bias = sbias[kkg * 7 + i];
            unsigned long long bd = pk2f(bias, bias);
            #pragma unroll
            for (int j = 0; j < 4; j++) {
                F2 r; r.u = add2(kacc[i][j], bd);
                *(float2*)&hsk[(kkg * 7 + i) * 224 + 2 * pixg + 56 * j] = r.f;
            }
        }
    }
    __syncthreads();

    // ---- Phase 2: apply. thread = pixel-pair x 8 channels ----
    if (tid < 224) {
        const int pp = tid >> 1;        // 0..111
        const int hh = tid & 1;         // channel half
        const int lr = pp / 28;         // 0..3
        const int pc = pp - lr * 28;    // 0..27
        const int pix0 = 2 * pp;        // = lr*56 + 2*pc
        const int row = r0 + lr;

        unsigned long long acc[8];
        #pragma unroll
        for (int i = 0; i < 8; i++) acc[i] = 0ull;

        #pragma unroll 1
        for (int kh = 0; kh < 7; kh++) {
            unsigned long long kc2[7];
            #pragma unroll
            for (int kw = 0; kw < 7; kw++) {
                F2 t; t.f = *(const float2*)&hsk[(kh * 7 + kw) * 224 + pix0];
                kc2[kw] = t.u;
            }
            #pragma unroll
            for (int i = 0; i < 8; i++) {
                const int ch = hh * 8 + i;
                const float* xr = &xt[ch * XCH + (lr + kh) * 62 + 2 * pc];
                F2 P[4];
                #pragma unroll
                for (int s = 0; s < 4; s++) P[s].f = *(const float2*)&xr[2 * s];
                unsigned long long M[3];
                #pragma unroll
                for (int s = 0; s < 3; s++) M[s] = pk2f(P[s].f.y, P[s + 1].f.x);

                acc[i] = ffma2(kc2[0], P[0].u, acc[i]);
                acc[i] = ffma2(kc2[1], M[0],   acc[i]);
                acc[i] = ffma2(kc2[2], P[1].u, acc[i]);
                acc[i] = ffma2(kc2[3], M[1],   acc[i]);
                acc[i] = ffma2(kc2[4], P[2].u, acc[i]);
                acc[i] = ffma2(kc2[5], M[2],   acc[i]);
                acc[i] = ffma2(kc2[6], P[3].u, acc[i]);
            }
        }

        #pragma unroll
        for (int i = 0; i < 8; i++) {
            const int ch = hh * 8 + i;
            F2 r; r.u = acc[i];
            *(float2*)&out[(b * 256 + g * 16 + ch) * HW + row * 56 + 2 * pc] = r.f;
        }
    }
}

extern "C" void kernel_launch(void* const* d_in, const int* in_sizes, int n_in,
                              void* d_out, int out_size)
{
    const float* x  = (const float*)d_in[0];
    const float* rw = (const float*)d_in[1];
    const float* rb = (const float*)d_in[2];
    const float* sw = (const float*)d_in[3];
    const float* sb = (const float*)d_in[4];
    float* out = (float*)d_out;

    const int smem2 = (3136 + 64 + 64 * 224 + 16 * XCH) * sizeof(float); // ~111 KB
    cudaFuncSetAttribute(inv_kernel, cudaFuncAttributeMaxDynamicSharedMemorySize, smem2);

    reduce_kernel<<<dim3(28, 4), 256>>>(x, rw, rb);
    inv_kernel<<<dim3(14, 16, 4), 256, smem2>>>(x, sw, sb, out);
}